// round 5
// baseline (speedup 1.0000x reference)
#include <cuda_runtime.h>
#include <cuda_bf16.h>
#include <math.h>

#define GG 128
#define NN 512
#define NV (GG*NN)          // 65536 nodes
#define HH 128              // hidden/feature dim
#define EE 2097152          // directed edges (2 * G * E_HALF)
#define EHALF 8192
#define EPG 16384           // directed edges per graph
#define LL 5
#define CC 10

// Scratch (device globals: allocation-free per harness rules)
__device__ float    g_bufA[NV * HH];        // 32 MB
__device__ float    g_bufB[NV * HH];        // 32 MB
__device__ int      g_row_ptr[NV + 1];
__device__ int      g_edge_off[EE];         // 8 MB: local src byte offsets (32-float rows)
__device__ unsigned g_Wth[LL * HH * 64];    // W^T hi, packed bf16 k-pairs [l][n][kw]
__device__ unsigned g_Wtl[LL * HH * 64];    // W^T lo

// ---------------------------------------------------------------- fused CSR build
// One CTA per graph: counting sort of that graph's 16384 directed edges by dst.
// Emits edge SOURCE as pre-scaled local byte offset: (src % 512) * 128 bytes
// (the SpMM smem slice rows are 32 floats = 128 B).
__global__ void __launch_bounds__(512) k_csr(const int* __restrict__ src,
                                             const int* __restrict__ dst) {
    __shared__ int cnt[NN];
    __shared__ int pos[NN];
    int g = blockIdx.x, t = threadIdx.x;
    cnt[t] = 0;
    __syncthreads();

    int base1 = g * EHALF;
    int base2 = GG * EHALF + g * EHALF;
    for (int i = t; i < EHALF; i += 512) {
        atomicAdd(&cnt[dst[base1 + i] & (NN - 1)], 1);
        atomicAdd(&cnt[dst[base2 + i] & (NN - 1)], 1);
    }
    __syncthreads();

    int c = cnt[t];
    pos[t] = c;
    __syncthreads();
    for (int off = 1; off < NN; off <<= 1) {
        int v = (t >= off) ? pos[t - off] : 0;
        __syncthreads();
        pos[t] += v;
        __syncthreads();
    }
    int startLocal = pos[t] - c;               // exclusive prefix within graph
    g_row_ptr[g * NN + t] = g * EPG + startLocal;
    cnt[t] = startLocal;                       // local scatter cursor
    if (g == 0 && t == 0) g_row_ptr[NV] = EE;
    __syncthreads();

    int* eout = g_edge_off + g * EPG;
    for (int i = t; i < EHALF; i += 512) {
        int d = dst[base1 + i] & (NN - 1);
        int p = atomicAdd(&cnt[d], 1);
        eout[p] = (src[base1 + i] & (NN - 1)) << 7;
        d = dst[base2 + i] & (NN - 1);
        p = atomicAdd(&cnt[d], 1);
        eout[p] = (src[base2 + i] & (NN - 1)) << 7;
    }
}

// ---------------------------------------------------------------- W prep: transpose + bf16 hi/lo split
// g_Wth[l][n][kw] = bf16x2{ W[l][2kw][n], W[l][2kw+1][n] }  (hi); g_Wtl = residual.
__global__ void k_prepw(const float* __restrict__ W) {
    int i = blockIdx.x * blockDim.x + threadIdx.x;
    if (i >= LL * HH * 64) return;
    int kw = i & 63;
    int n  = (i >> 6) & (HH - 1);
    int l  = i >> 13;
    const float* Wl = W + l * HH * HH;
    float w0 = Wl[(2 * kw) * HH + n];
    float w1 = Wl[(2 * kw + 1) * HH + n];
    __nv_bfloat162 h = __float22bfloat162_rn(make_float2(w0, w1));
    float2 hf = __bfloat1622float2(h);
    __nv_bfloat162 lo = __float22bfloat162_rn(make_float2(w0 - hf.x, w1 - hf.y));
    g_Wth[i] = *reinterpret_cast<unsigned*>(&h);
    g_Wtl[i] = *reinterpret_cast<unsigned*>(&lo);
}

// ---------------------------------------------------------------- SpMM: smem-resident gather
// 4 CTAs per graph, each owns a 32-feature slice of all 512 nodes in smem (64 KB).
// U[v] = (1+eps)*h[v] + sum_{e: dst=v} h[src[e]]  -- fp32 exact.
#define SPMM_SMEM (NN*32*4 + (NN+1)*4 + 16)

__global__ void __launch_bounds__(512) k_spmm_s(const float* __restrict__ xin,
                                                const float* __restrict__ eps,
                                                int layer, int ssel, int dsel) {
    const float* hin  = (ssel == 0) ? xin : (ssel == 1 ? g_bufA : g_bufB);
    float*       uout = (dsel == 1) ? g_bufA : g_bufB;

    extern __shared__ char dsm[];
    float* sF  = (float*)dsm;                 // [512][32]
    int*   sRP = (int*)(dsm + NN * 32 * 4);   // [513]

    int bid = blockIdx.x;
    int g = bid >> 2, s = bid & 3;
    int t = threadIdx.x;

    // stage feature slice: node n -> sF[n][0..31] = h[g*512+n][s*32 .. +32)
    {
        const float4* h4 = (const float4*)(hin + (size_t)g * NN * HH);
        float4* sF4 = (float4*)sF;
#pragma unroll
        for (int k = 0; k < 8; k++) {
            int q = t + k * 512;              // 4096 float4
            int n = q >> 3, c = q & 7;
            sF4[q] = h4[n * 32 + s * 8 + c];
        }
    }
    sRP[t] = g_row_ptr[g * NN + t] - g * EPG;
    if (t == 0) sRP[NN] = EPG;
    __syncthreads();

    const int* eo = g_edge_off + g * EPG;
    int w = t >> 5, lane = t & 31;
    float e1 = 1.0f + __ldg(&eps[layer]);
    const char* sFb = (const char*)sF + lane * 4;

#pragma unroll 1
    for (int i = 0; i < 32; i++) {
        int n = i * 16 + w;
        float acc = e1 * sF[n * 32 + lane];
        int e = sRP[n], eend = sRP[n + 1];
        for (; e + 4 <= eend; e += 4) {
            int o0 = eo[e], o1 = eo[e + 1], o2 = eo[e + 2], o3 = eo[e + 3];
            acc += *(const float*)(sFb + o0);
            acc += *(const float*)(sFb + o1);
            acc += *(const float*)(sFb + o2);
            acc += *(const float*)(sFb + o3);
        }
        for (; e < eend; e++) acc += *(const float*)(sFb + eo[e]);
        uout[((size_t)g * NN + n) * HH + s * 32 + lane] = acc;
    }
}

// ---------------------------------------------------------------- tensor-core GEMM + bias + relu
// h = relu(U @ W_l + b_l), in place. 3-pass bf16 split (Uh*Wh + Ul*Wh + Uh*Wl), fp32 accum.
// CTA 256 thr = 8 warps (2 x 4); tile 64 rows x 128 cols; warp 32 x 32.
// All fragments via ldmatrix.x4; U split to bf16 hi/lo at stage time.

#define SW 136   // bf16 elems per smem row (128 + 8 pad -> 272 B stride, ldmatrix conflict-free)
#define SMEM_GEMM ((64*SW + 64*SW + HH*SW + HH*SW) * 2 + HH * 4)

#define MMA_BF16(C, A0, A1, A2, A3, B0, B1)                                      \
    asm volatile("mma.sync.aligned.m16n8k16.row.col.f32.bf16.bf16.f32 "          \
                 "{%0,%1,%2,%3}, {%4,%5,%6,%7}, {%8,%9}, {%0,%1,%2,%3};"         \
                 : "+f"(C[0]), "+f"(C[1]), "+f"(C[2]), "+f"(C[3])                \
                 : "r"(A0), "r"(A1), "r"(A2), "r"(A3), "r"(B0), "r"(B1))

#define LDMX4(R, addr)                                                           \
    asm volatile("ldmatrix.sync.aligned.m8n8.x4.shared.b16 {%0,%1,%2,%3}, [%4];" \
                 : "=r"(R[0]), "=r"(R[1]), "=r"(R[2]), "=r"(R[3]) : "r"(addr))

__global__ void __launch_bounds__(256) k_gemm_tc(const float* __restrict__ b,
                                                 int layer, int bufsel) {
    float* u = (bufsel == 1) ? g_bufA : g_bufB;

    extern __shared__ char smem[];
    __nv_bfloat16* sUh = (__nv_bfloat16*)smem;
    __nv_bfloat16* sUl = sUh + 64 * SW;
    __nv_bfloat16* sWh = sUl + 64 * SW;
    __nv_bfloat16* sWl = sWh + HH * SW;
    float*         sB  = (float*)(sWl + HH * SW);

    int tid = threadIdx.x;
    int rowBase = blockIdx.x * 64;

    // ---- stage U (fp32 -> bf16 hi/lo planes) ----
    {
        const float4* u4 = (const float4*)(u + (size_t)rowBase * HH);
#pragma unroll
        for (int k = 0; k < 8; k++) {
            int q = tid + k * 256;            // 2048 float4
            int r = q >> 5, c = (q & 31) * 4;
            float4 v = u4[q];
            __nv_bfloat162 h01 = __float22bfloat162_rn(make_float2(v.x, v.y));
            __nv_bfloat162 h23 = __float22bfloat162_rn(make_float2(v.z, v.w));
            float2 f01 = __bfloat1622float2(h01);
            float2 f23 = __bfloat1622float2(h23);
            __nv_bfloat162 l01 = __float22bfloat162_rn(make_float2(v.x - f01.x, v.y - f01.y));
            __nv_bfloat162 l23 = __float22bfloat162_rn(make_float2(v.z - f23.x, v.w - f23.y));
            uint2 hw, lw;
            hw.x = *(unsigned*)&h01; hw.y = *(unsigned*)&h23;
            lw.x = *(unsigned*)&l01; lw.y = *(unsigned*)&l23;
            *(uint2*)(sUh + r * SW + c) = hw;
            *(uint2*)(sUl + r * SW + c) = lw;
        }
    }
    // ---- stage W hi/lo (already packed bf16 [n][k]) ----
    {
        const uint4* wh4 = (const uint4*)(g_Wth + layer * HH * 64);
        const uint4* wl4 = (const uint4*)(g_Wtl + layer * HH * 64);
#pragma unroll
        for (int k = 0; k < 8; k++) {
            int q = tid + k * 256;            // 2048 uint4
            int n = q >> 4, cw = (q & 15) * 4;
            *(uint4*)(sWh + n * SW + cw * 2) = wh4[q];
            *(uint4*)(sWl + n * SW + cw * 2) = wl4[q];
        }
    }
    if (tid < HH) sB[tid] = b[layer * HH + tid];
    __syncthreads();

    int warp = tid >> 5, lane = tid & 31;
    int wm = warp & 1, wn = warp >> 1;
    int rw = wm * 32, nw = wn * 32;

    float acc[2][4][4];
#pragma unroll
    for (int mt = 0; mt < 2; mt++)
#pragma unroll
        for (int j = 0; j < 4; j++)
#pragma unroll
            for (int q = 0; q < 4; q++) acc[mt][j][q] = 0.f;

    // ldmatrix lane addressing
    int lb = lane >> 3, lr = lane & 7;
    int a_row = (lb & 1) * 8 + lr;            // blocks: r0k0, r8k0, r0k8, r8k8
    int a_k   = (lb >> 1) * 8;
    int b_n   = (lb >> 1) * 8 + lr;           // blocks: n0k0, n0k8, n8k0, n8k8
    int b_k   = (lb & 1) * 8;

    unsigned aH[2], aL[2], bH[2], bL[2];
#pragma unroll
    for (int mt = 0; mt < 2; mt++) {
        int row = rw + mt * 16 + a_row;
        aH[mt] = (unsigned)__cvta_generic_to_shared(sUh + row * SW + a_k);
        aL[mt] = (unsigned)__cvta_generic_to_shared(sUl + row * SW + a_k);
    }
#pragma unroll
    for (int jp = 0; jp < 2; jp++) {
        int n = nw + jp * 16 + b_n;
        bH[jp] = (unsigned)__cvta_generic_to_shared(sWh + n * SW + b_k);
        bL[jp] = (unsigned)__cvta_generic_to_shared(sWl + n * SW + b_k);
    }

#pragma unroll
    for (int ks = 0; ks < 8; ks++) {
        unsigned ko = ks * 32;                // 16 bf16 = 32 bytes
        unsigned Ah[2][4], Al[2][4];
        LDMX4(Ah[0], aH[0] + ko); LDMX4(Ah[1], aH[1] + ko);
        LDMX4(Al[0], aL[0] + ko); LDMX4(Al[1], aL[1] + ko);
#pragma unroll
        for (int jp = 0; jp < 2; jp++) {
            unsigned Bh[4], Bl[4];
            LDMX4(Bh, bH[jp] + ko);
            LDMX4(Bl, bL[jp] + ko);
#pragma unroll
            for (int mt = 0; mt < 2; mt++) {
#pragma unroll
                for (int jj = 0; jj < 2; jj++) {
                    int j = jp * 2 + jj;
                    MMA_BF16(acc[mt][j], Ah[mt][0], Ah[mt][1], Ah[mt][2], Ah[mt][3],
                             Bh[jj * 2], Bh[jj * 2 + 1]);
                    MMA_BF16(acc[mt][j], Al[mt][0], Al[mt][1], Al[mt][2], Al[mt][3],
                             Bh[jj * 2], Bh[jj * 2 + 1]);
                    MMA_BF16(acc[mt][j], Ah[mt][0], Ah[mt][1], Ah[mt][2], Ah[mt][3],
                             Bl[jj * 2], Bl[jj * 2 + 1]);
                }
            }
        }
    }

    // ---- epilogue: bias + relu, store fp32 in place ----
    int g2 = lane >> 2, tg = lane & 3;
#pragma unroll
    for (int mt = 0; mt < 2; mt++) {
        int rA = rowBase + rw + mt * 16 + g2;
        int rB = rA + 8;
#pragma unroll
        for (int j = 0; j < 4; j++) {
            int c = nw + j * 8 + 2 * tg;
            float b0 = sB[c], b1 = sB[c + 1];
            float2 oA, oB;
            oA.x = fmaxf(acc[mt][j][0] + b0, 0.f);
            oA.y = fmaxf(acc[mt][j][1] + b1, 0.f);
            oB.x = fmaxf(acc[mt][j][2] + b0, 0.f);
            oB.y = fmaxf(acc[mt][j][3] + b1, 0.f);
            *(float2*)(u + (size_t)rA * HH + c) = oA;
            *(float2*)(u + (size_t)rB * HH + c) = oB;
        }
    }
}

// ---------------------------------------------------------------- readout + FCs + softmax
__global__ void __launch_bounds__(256) k_readout(const float* __restrict__ fc1w,
                                                 const float* __restrict__ fc1b,
                                                 const float* __restrict__ fc2w,
                                                 const float* __restrict__ fc2b,
                                                 float* __restrict__ out,
                                                 int bufsel) {
    const float* h = (bufsel == 1) ? g_bufA : g_bufB;
    __shared__ float tmp[256];
    __shared__ float hg[HH];
    __shared__ float a1[HH];
    __shared__ float z[CC];
    __shared__ float ez[CC];

    int g = blockIdx.x;
    int t = threadIdx.x;
    int f = t & 127, half = t >> 7;

    const float* base = h + (size_t)g * NN * HH + half * 256 * HH + f;
    float s = 0.f;
#pragma unroll 8
    for (int r = 0; r < 256; r++) s += base[r * HH];
    tmp[t] = s;
    __syncthreads();
    if (half == 0) hg[f] = tmp[f] + tmp[f + 128];
    __syncthreads();

    if (t < HH) {
        float acc = fc1b[t];
        for (int k = 0; k < HH; k++) acc += hg[k] * __ldg(&fc1w[k * HH + t]);
        a1[t] = fmaxf(acc, 0.f);
    }
    __syncthreads();

    if (t < CC) {
        float acc = fc2b[t];
        for (int k = 0; k < HH; k++) acc += a1[k] * __ldg(&fc2w[k * CC + t]);
        z[t] = acc;
    }
    __syncthreads();

    if (t < CC) {
        float m = z[0];
#pragma unroll
        for (int j = 1; j < CC; j++) m = fmaxf(m, z[j]);
        ez[t] = expf(z[t] - m);
    }
    __syncthreads();

    if (t < CC) {
        float ssum = 0.f;
#pragma unroll
        for (int j = 0; j < CC; j++) ssum += ez[j];
        out[g * CC + t] = ez[t] / ssum;
    }
}

// ---------------------------------------------------------------- launch
extern "C" void kernel_launch(void* const* d_in, const int* in_sizes, int n_in,
                              void* d_out, int out_size) {
    const float* x    = (const float*)d_in[0];
    const float* eps  = (const float*)d_in[1];
    const float* W    = (const float*)d_in[2];
    const float* b    = (const float*)d_in[3];
    const float* fc1w = (const float*)d_in[4];
    const float* fc1b = (const float*)d_in[5];
    const float* fc2w = (const float*)d_in[6];
    const float* fc2b = (const float*)d_in[7];
    const int*   src  = (const int*)d_in[8];
    const int*   dst  = (const int*)d_in[9];
    float* out = (float*)d_out;

    cudaFuncSetAttribute(k_gemm_tc, cudaFuncAttributeMaxDynamicSharedMemorySize,
                         SMEM_GEMM);
    cudaFuncSetAttribute(k_spmm_s, cudaFuncAttributeMaxDynamicSharedMemorySize,
                         SPMM_SMEM);

    k_csr<<<GG, 512>>>(src, dst);
    k_prepw<<<(LL * HH * 64 + 255) / 256, 256>>>(W);

    // 0: x->A, 1: A->B, 2: B->A, 3: A->B, 4: B->A. Final h in A.
    const int ssel[LL] = {0, 1, 2, 1, 2};
    const int dsel[LL] = {1, 2, 1, 2, 1};
    for (int l = 0; l < LL; l++) {
        k_spmm_s<<<GG * 4, 512, SPMM_SMEM>>>(x, eps, l, ssel[l], dsel[l]);
        k_gemm_tc<<<NV / 64, 256, SMEM_GEMM>>>(b, l, dsel[l]);
    }

    k_readout<<<GG, 256>>>(fc1w, fc1b, fc2w, fc2b, out, 1);
}

// round 6
// speedup vs baseline: 1.4470x; 1.4470x over previous
#include <cuda_runtime.h>
#include <cuda_bf16.h>
#include <math.h>

#define GG 128
#define NN 512
#define NV (GG*NN)          // 65536 nodes
#define HH 128              // hidden/feature dim
#define EE 2097152          // directed edges (2 * G * E_HALF)
#define EHALF 8192
#define EPG 16384           // directed edges per graph
#define LL 5
#define CC 10

// Scratch (device globals: allocation-free per harness rules)
__device__ float    g_bufA[NV * HH];        // 32 MB
__device__ float    g_bufB[NV * HH];        // 32 MB
__device__ int      g_row_ptr[NV + 1];
__device__ int      g_edge_off[EE];         // 8 MB: local src index * 32 (float4 row offset)
__device__ unsigned g_Wth[LL * HH * 64];    // W^T hi, packed bf16 k-pairs [l][n][kw]
__device__ unsigned g_Wtl[LL * HH * 64];    // W^T lo

// ---------------------------------------------------------------- fused CSR build
// One CTA per graph: counting sort of that graph's 16384 directed edges by dst.
// Emits src as LOCAL index * 32 (pre-scaled float4-row offset).
__global__ void __launch_bounds__(512) k_csr(const int* __restrict__ src,
                                             const int* __restrict__ dst) {
    __shared__ int cnt[NN];
    __shared__ int pos[NN];
    int g = blockIdx.x, t = threadIdx.x;
    cnt[t] = 0;
    __syncthreads();

    int base1 = g * EHALF;
    int base2 = GG * EHALF + g * EHALF;
    for (int i = t; i < EHALF; i += 512) {
        atomicAdd(&cnt[dst[base1 + i] & (NN - 1)], 1);
        atomicAdd(&cnt[dst[base2 + i] & (NN - 1)], 1);
    }
    __syncthreads();

    int c = cnt[t];
    pos[t] = c;
    __syncthreads();
    for (int off = 1; off < NN; off <<= 1) {
        int v = (t >= off) ? pos[t - off] : 0;
        __syncthreads();
        pos[t] += v;
        __syncthreads();
    }
    int startLocal = pos[t] - c;               // exclusive prefix within graph
    g_row_ptr[g * NN + t] = g * EPG + startLocal;
    cnt[t] = startLocal;                       // local scatter cursor
    if (g == 0 && t == 0) g_row_ptr[NV] = EE;
    __syncthreads();

    int* eout = g_edge_off + g * EPG;
    for (int i = t; i < EHALF; i += 512) {
        int d = dst[base1 + i] & (NN - 1);
        int p = atomicAdd(&cnt[d], 1);
        eout[p] = (src[base1 + i] & (NN - 1)) * 32;
        d = dst[base2 + i] & (NN - 1);
        p = atomicAdd(&cnt[d], 1);
        eout[p] = (src[base2 + i] & (NN - 1)) * 32;
    }
}

// ---------------------------------------------------------------- W prep: transpose + bf16 hi/lo split
__global__ void k_prepw(const float* __restrict__ W) {
    int i = blockIdx.x * blockDim.x + threadIdx.x;
    if (i >= LL * HH * 64) return;
    int kw = i & 63;
    int n  = (i >> 6) & (HH - 1);
    int l  = i >> 13;
    const float* Wl = W + l * HH * HH;
    float w0 = Wl[(2 * kw) * HH + n];
    float w1 = Wl[(2 * kw + 1) * HH + n];
    __nv_bfloat162 h = __float22bfloat162_rn(make_float2(w0, w1));
    float2 hf = __bfloat1622float2(h);
    __nv_bfloat162 lo = __float22bfloat162_rn(make_float2(w0 - hf.x, w1 - hf.y));
    g_Wth[i] = *reinterpret_cast<unsigned*>(&h);
    g_Wtl[i] = *reinterpret_cast<unsigned*>(&lo);
}

// ---------------------------------------------------------------- SpMM + combine (R3 structure)
// One warp per node: lane owns one float4 (4 of 128 feats). L1-resident gather.
__global__ void __launch_bounds__(256) k_spmm(const float* __restrict__ xin,
                                              const float* __restrict__ eps,
                                              int layer, int ssel, int dsel) {
    const float* hin  = (ssel == 0) ? xin : (ssel == 1 ? g_bufA : g_bufB);
    float*       uout = (dsel == 1) ? g_bufA : g_bufB;

    int wid  = (blockIdx.x * blockDim.x + threadIdx.x) >> 5;
    int lane = threadIdx.x & 31;
    if (wid >= NV) return;

    int g = wid >> 9;                                   // graph id
    const float4* hg4 = (const float4*)hin + (size_t)g * NN * 32;

    float e1 = 1.0f + __ldg(&eps[layer]);
    int base = wid * 32 + lane;

    float4 h0 = ((const float4*)hin)[base];
    float4 acc;
    acc.x = e1 * h0.x; acc.y = e1 * h0.y; acc.z = e1 * h0.z; acc.w = e1 * h0.w;

    int e    = g_row_ptr[wid];
    int eend = g_row_ptr[wid + 1];

    for (; e + 4 <= eend; e += 4) {
        int o0 = g_edge_off[e + 0];
        int o1 = g_edge_off[e + 1];
        int o2 = g_edge_off[e + 2];
        int o3 = g_edge_off[e + 3];
        float4 f0 = hg4[o0 + lane];
        float4 f1 = hg4[o1 + lane];
        float4 f2 = hg4[o2 + lane];
        float4 f3 = hg4[o3 + lane];
        acc.x += f0.x; acc.y += f0.y; acc.z += f0.z; acc.w += f0.w;
        acc.x += f1.x; acc.y += f1.y; acc.z += f1.z; acc.w += f1.w;
        acc.x += f2.x; acc.y += f2.y; acc.z += f2.z; acc.w += f2.w;
        acc.x += f3.x; acc.y += f3.y; acc.z += f3.z; acc.w += f3.w;
    }
    for (; e < eend; e++) {
        float4 f0 = hg4[g_edge_off[e] + lane];
        acc.x += f0.x; acc.y += f0.y; acc.z += f0.z; acc.w += f0.w;
    }
    ((float4*)uout)[base] = acc;
}

// ---------------------------------------------------------------- tensor-core GEMM + bias + relu
// h = relu(U @ W_l + b_l), in place. 3-pass bf16 split, fp32 accum.
// CTA 256 thr = 8 warps (2 x 4); tile 64 rows x 128 cols; warp 32 x 32.
// Register double-buffered ldmatrix pipeline; reg cap 128 via launch_bounds(256,2).

#define SW 136   // bf16 elems per smem row (272 B stride, ldmatrix conflict-free)
#define SMEM_GEMM ((64*SW + 64*SW + HH*SW + HH*SW) * 2 + HH * 4)

#define MMA_BF16(C, A0, A1, A2, A3, B0, B1)                                      \
    asm volatile("mma.sync.aligned.m16n8k16.row.col.f32.bf16.bf16.f32 "          \
                 "{%0,%1,%2,%3}, {%4,%5,%6,%7}, {%8,%9}, {%0,%1,%2,%3};"         \
                 : "+f"(C[0]), "+f"(C[1]), "+f"(C[2]), "+f"(C[3])                \
                 : "r"(A0), "r"(A1), "r"(A2), "r"(A3), "r"(B0), "r"(B1))

#define LDMX4(R, addr)                                                           \
    asm volatile("ldmatrix.sync.aligned.m8n8.x4.shared.b16 {%0,%1,%2,%3}, [%4];" \
                 : "=r"(R[0]), "=r"(R[1]), "=r"(R[2]), "=r"(R[3]) : "r"(addr))

#define LDFRAGS(buf, ks)                                                         \
    do {                                                                         \
        unsigned _ko = (unsigned)(ks) * 32;                                      \
        LDMX4(AH[buf][0], aH[0] + _ko); LDMX4(AH[buf][1], aH[1] + _ko);          \
        LDMX4(AL[buf][0], aL[0] + _ko); LDMX4(AL[buf][1], aL[1] + _ko);          \
        LDMX4(BH[buf][0], bH[0] + _ko); LDMX4(BH[buf][1], bH[1] + _ko);          \
        LDMX4(BL[buf][0], bL[0] + _ko); LDMX4(BL[buf][1], bL[1] + _ko);          \
    } while (0)

__global__ void __launch_bounds__(256, 2) k_gemm_tc(const float* __restrict__ b,
                                                    int layer, int bufsel) {
    float* u = (bufsel == 1) ? g_bufA : g_bufB;

    extern __shared__ char smem[];
    __nv_bfloat16* sUh = (__nv_bfloat16*)smem;
    __nv_bfloat16* sUl = sUh + 64 * SW;
    __nv_bfloat16* sWh = sUl + 64 * SW;
    __nv_bfloat16* sWl = sWh + HH * SW;
    float*         sB  = (float*)(sWl + HH * SW);

    int tid = threadIdx.x;
    int rowBase = blockIdx.x * 64;

    // ---- stage U (fp32 -> bf16 hi/lo planes) ----
    {
        const float4* u4 = (const float4*)(u + (size_t)rowBase * HH);
#pragma unroll
        for (int k = 0; k < 8; k++) {
            int q = tid + k * 256;            // 2048 float4
            int r = q >> 5, c = (q & 31) * 4;
            float4 v = u4[q];
            __nv_bfloat162 h01 = __float22bfloat162_rn(make_float2(v.x, v.y));
            __nv_bfloat162 h23 = __float22bfloat162_rn(make_float2(v.z, v.w));
            float2 f01 = __bfloat1622float2(h01);
            float2 f23 = __bfloat1622float2(h23);
            __nv_bfloat162 l01 = __float22bfloat162_rn(make_float2(v.x - f01.x, v.y - f01.y));
            __nv_bfloat162 l23 = __float22bfloat162_rn(make_float2(v.z - f23.x, v.w - f23.y));
            uint2 hw, lw;
            hw.x = *(unsigned*)&h01; hw.y = *(unsigned*)&h23;
            lw.x = *(unsigned*)&l01; lw.y = *(unsigned*)&l23;
            *(uint2*)(sUh + r * SW + c) = hw;
            *(uint2*)(sUl + r * SW + c) = lw;
        }
    }
    // ---- stage W hi/lo (already packed bf16 [n][k]) ----
    {
        const uint4* wh4 = (const uint4*)(g_Wth + layer * HH * 64);
        const uint4* wl4 = (const uint4*)(g_Wtl + layer * HH * 64);
#pragma unroll
        for (int k = 0; k < 8; k++) {
            int q = tid + k * 256;            // 2048 uint4
            int n = q >> 4, cw = (q & 15) * 4;
            *(uint4*)(sWh + n * SW + cw * 2) = wh4[q];
            *(uint4*)(sWl + n * SW + cw * 2) = wl4[q];
        }
    }
    if (tid < HH) sB[tid] = b[layer * HH + tid];
    __syncthreads();

    int warp = tid >> 5, lane = tid & 31;
    int wm = warp & 1, wn = warp >> 1;
    int rw = wm * 32, nw = wn * 32;

    float acc[2][4][4];
#pragma unroll
    for (int mt = 0; mt < 2; mt++)
#pragma unroll
        for (int j = 0; j < 4; j++)
#pragma unroll
            for (int q = 0; q < 4; q++) acc[mt][j][q] = 0.f;

    // ldmatrix lane addressing
    int lb = lane >> 3, lr = lane & 7;
    int a_row = (lb & 1) * 8 + lr;            // blocks: r0k0, r8k0, r0k8, r8k8
    int a_k   = (lb >> 1) * 8;
    int b_n   = (lb >> 1) * 8 + lr;           // blocks: n0k0, n0k8, n8k0, n8k8
    int b_k   = (lb & 1) * 8;

    unsigned aH[2], aL[2], bH[2], bL[2];
#pragma unroll
    for (int mt = 0; mt < 2; mt++) {
        int row = rw + mt * 16 + a_row;
        aH[mt] = (unsigned)__cvta_generic_to_shared(sUh + row * SW + a_k);
        aL[mt] = (unsigned)__cvta_generic_to_shared(sUl + row * SW + a_k);
    }
#pragma unroll
    for (int jp = 0; jp < 2; jp++) {
        int n = nw + jp * 16 + b_n;
        bH[jp] = (unsigned)__cvta_generic_to_shared(sWh + n * SW + b_k);
        bL[jp] = (unsigned)__cvta_generic_to_shared(sWl + n * SW + b_k);
    }

    // register double-buffered fragment pipeline
    unsigned AH[2][2][4], AL[2][2][4], BH[2][2][4], BL[2][2][4];
    LDFRAGS(0, 0);
#pragma unroll
    for (int ks = 0; ks < 8; ks++) {
        int cur = ks & 1, nxt = cur ^ 1;
        if (ks < 7) LDFRAGS(nxt, ks + 1);
#pragma unroll
        for (int jp = 0; jp < 2; jp++) {
#pragma unroll
            for (int mt = 0; mt < 2; mt++) {
#pragma unroll
                for (int jj = 0; jj < 2; jj++) {
                    int j = jp * 2 + jj;
                    MMA_BF16(acc[mt][j],
                             AH[cur][mt][0], AH[cur][mt][1], AH[cur][mt][2], AH[cur][mt][3],
                             BH[cur][jp][jj * 2], BH[cur][jp][jj * 2 + 1]);
                    MMA_BF16(acc[mt][j],
                             AL[cur][mt][0], AL[cur][mt][1], AL[cur][mt][2], AL[cur][mt][3],
                             BH[cur][jp][jj * 2], BH[cur][jp][jj * 2 + 1]);
                    MMA_BF16(acc[mt][j],
                             AH[cur][mt][0], AH[cur][mt][1], AH[cur][mt][2], AH[cur][mt][3],
                             BL[cur][jp][jj * 2], BL[cur][jp][jj * 2 + 1]);
                }
            }
        }
    }

    // ---- epilogue: bias + relu, store fp32 in place ----
    int g2 = lane >> 2, tg = lane & 3;
#pragma unroll
    for (int mt = 0; mt < 2; mt++) {
        int rA = rowBase + rw + mt * 16 + g2;
        int rB = rA + 8;
#pragma unroll
        for (int j = 0; j < 4; j++) {
            int c = nw + j * 8 + 2 * tg;
            float b0 = sB[c], b1 = sB[c + 1];
            float2 oA, oB;
            oA.x = fmaxf(acc[mt][j][0] + b0, 0.f);
            oA.y = fmaxf(acc[mt][j][1] + b1, 0.f);
            oB.x = fmaxf(acc[mt][j][2] + b0, 0.f);
            oB.y = fmaxf(acc[mt][j][3] + b1, 0.f);
            *(float2*)(u + (size_t)rA * HH + c) = oA;
            *(float2*)(u + (size_t)rB * HH + c) = oB;
        }
    }
}

// ---------------------------------------------------------------- readout + FCs + softmax
__global__ void __launch_bounds__(256) k_readout(const float* __restrict__ fc1w,
                                                 const float* __restrict__ fc1b,
                                                 const float* __restrict__ fc2w,
                                                 const float* __restrict__ fc2b,
                                                 float* __restrict__ out,
                                                 int bufsel) {
    const float* h = (bufsel == 1) ? g_bufA : g_bufB;
    __shared__ float tmp[256];
    __shared__ float hg[HH];
    __shared__ float a1[HH];
    __shared__ float z[CC];
    __shared__ float ez[CC];

    int g = blockIdx.x;
    int t = threadIdx.x;
    int f = t & 127, half = t >> 7;

    const float* base = h + (size_t)g * NN * HH + half * 256 * HH + f;
    float s = 0.f;
#pragma unroll 8
    for (int r = 0; r < 256; r++) s += base[r * HH];
    tmp[t] = s;
    __syncthreads();
    if (half == 0) hg[f] = tmp[f] + tmp[f + 128];
    __syncthreads();

    if (t < HH) {
        float acc = fc1b[t];
        for (int k = 0; k < HH; k++) acc += hg[k] * __ldg(&fc1w[k * HH + t]);
        a1[t] = fmaxf(acc, 0.f);
    }
    __syncthreads();

    if (t < CC) {
        float acc = fc2b[t];
        for (int k = 0; k < HH; k++) acc += a1[k] * __ldg(&fc2w[k * CC + t]);
        z[t] = acc;
    }
    __syncthreads();

    if (t < CC) {
        float m = z[0];
#pragma unroll
        for (int j = 1; j < CC; j++) m = fmaxf(m, z[j]);
        ez[t] = expf(z[t] - m);
    }
    __syncthreads();

    if (t < CC) {
        float ssum = 0.f;
#pragma unroll
        for (int j = 0; j < CC; j++) ssum += ez[j];
        out[g * CC + t] = ez[t] / ssum;
    }
}

// ---------------------------------------------------------------- launch
extern "C" void kernel_launch(void* const* d_in, const int* in_sizes, int n_in,
                              void* d_out, int out_size) {
    const float* x    = (const float*)d_in[0];
    const float* eps  = (const float*)d_in[1];
    const float* W    = (const float*)d_in[2];
    const float* b    = (const float*)d_in[3];
    const float* fc1w = (const float*)d_in[4];
    const float* fc1b = (const float*)d_in[5];
    const float* fc2w = (const float*)d_in[6];
    const float* fc2b = (const float*)d_in[7];
    const int*   src  = (const int*)d_in[8];
    const int*   dst  = (const int*)d_in[9];
    float* out = (float*)d_out;

    cudaFuncSetAttribute(k_gemm_tc, cudaFuncAttributeMaxDynamicSharedMemorySize,
                         SMEM_GEMM);

    k_csr<<<GG, 512>>>(src, dst);
    k_prepw<<<(LL * HH * 64 + 255) / 256, 256>>>(W);

    // 0: x->A, 1: A->B, 2: B->A, 3: A->B, 4: B->A. Final h in A.
    const int ssel[LL] = {0, 1, 2, 1, 2};
    const int dsel[LL] = {1, 2, 1, 2, 1};
    for (int l = 0; l < LL; l++) {
        k_spmm<<<NV / 8, 256>>>(x, eps, l, ssel[l], dsel[l]);
        k_gemm_tc<<<NV / 64, 256, SMEM_GEMM>>>(b, l, dsel[l]);
    }

    k_readout<<<GG, 256>>>(fc1w, fc1b, fc2w, fc2b, out, 1);
}